// round 7
// baseline (speedup 1.0000x reference)
#include <cuda_runtime.h>
#include <math_constants.h>

#define K 8
#define D 8
#define TRI 36
#define PHI_DIM 360         // K + K*D + K*TRI
#define M_MODELS 32
#define N_POINTS 32768
#define CHUNKS 64
#define THREADS 128
#define NPAIR 2             // 2 packed pairs = 4 points per thread
#define PSTRIDE 45          // per-(m,k): 36 Linv + 8 bias + 1 const (flat, R4 layout)

typedef unsigned long long ull;

// Scratch (no allocations allowed)
__device__ float g_partial[M_MODELS * CHUNKS];
__device__ int   g_count[M_MODELS];          // zero-init; self-resetting

__host__ __device__ __forceinline__ constexpr int tidx(int i, int j) {
    return i * (i + 1) / 2 + j;
}

// ---- packed f32x2 helpers ---------------------------------------------------
__device__ __forceinline__ ull pk2(float lo, float hi) {
    ull r; asm("mov.b64 %0,{%1,%2};" : "=l"(r) : "f"(lo), "f"(hi)); return r;
}
__device__ __forceinline__ void up2(ull v, float& lo, float& hi) {
    asm("mov.b64 {%0,%1},%2;" : "=f"(lo), "=f"(hi) : "l"(v));
}
__device__ __forceinline__ ull fma2(ull a, ull b, ull c) {
    ull r; asm("fma.rn.f32x2 %0,%1,%2,%3;" : "=l"(r) : "l"(a), "l"(b), "l"(c)); return r;
}
__device__ __forceinline__ float ex2a(float x) {
    float r; asm("ex2.approx.ftz.f32 %0,%1;" : "=f"(r) : "f"(x)); return r;
}
__device__ __forceinline__ float lg2a(float x) {
    float r; asm("lg2.approx.ftz.f32 %0,%1;" : "=f"(r) : "f"(x)); return r;
}

// ---------------------------------------------------------------------------
// Single fused kernel. grid = 32 models x 64 chunks = 2048 blocks x 128 thr,
// 7 CTAs/SM. Deferred logsumexp: all 8 component logits kept in registers
// (packed pairs), no serial dependence across the k loop.
// ---------------------------------------------------------------------------
__global__ void __launch_bounds__(THREADS, 7) fused_kernel(const float* __restrict__ phi,
                                                           const float* __restrict__ X,
                                                           float* __restrict__ out) {
    const int m = blockIdx.x >> 6;
    const int chunk = blockIdx.x & (CHUNKS - 1);
    const int tid = threadIdx.x;
    const float* pm = phi + m * PHI_DIM;

    __shared__ ull sp[K * PSTRIDE];
    __shared__ float red[THREADS];
    __shared__ float redp[THREADS];

    // ---- prior partial -------------------------------------------------------
    float pp = 0.f;
    #pragma unroll
    for (int i = tid; i < PHI_DIM; i += THREADS) {
        float v = pm[i];
        pp = fmaf(v, v, pp);
    }
    redp[tid] = pp;

    // ---- Stage A: build params in shared (threads 0-63, column-parallel) ----
    if (tid < 64) {
        const int k = tid >> 3;
        const int j = tid & 7;
        const float* Lk = pm + K + K * D + k * TRI;
        ull* dst = sp + k * PSTRIDE;
        const float SCALE = 0.8493218002880191f;  // sqrt(0.5*log2(e))

        float col[D];
        col[j] = __fdividef(1.f, Lk[tidx(j, j)]);
        for (int i = j + 1; i < D; ++i) {
            float acc = 0.f;
            for (int p = j; p < i; ++p)
                acc = fmaf(Lk[tidx(i, p)], col[p], acc);
            col[i] = -acc * __fdividef(1.f, Lk[tidx(i, i)]);
        }
        for (int i = j; i < D; ++i) {
            float v = col[i] * SCALE;
            dst[tidx(i, j)] = pk2(v, v);
        }

        if (j == 0) {
            float mx = -CUDART_INF_F;
            #pragma unroll
            for (int q = 0; q < K; ++q) mx = fmaxf(mx, pm[q]);
            float s = 0.f;
            #pragma unroll
            for (int q = 0; q < K; ++q) s += __expf(pm[q] - mx);
            const float log_pi = pm[k] - mx - __logf(s);

            float ld = 0.f;
            #pragma unroll
            for (int i = 0; i < D; ++i)
                ld += __logf(fmaxf(fabsf(Lk[tidx(i, i)]), 1e-8f));
            ld *= 2.f;

            const float c = log_pi - 0.5f * (D * 1.8378770664093453f + ld);
            const float c2 = c * 1.4426950408889634f;
            dst[TRI + D] = pk2(c2, c2);
        }
    }
    __syncthreads();

    // bias: nb_i = -sum_{j<=i} Linv_scaled[i][j] * mu[j]
    if (tid < 64) {
        const int k = tid >> 3;
        const int i = tid & 7;
        const float* mu = pm + K + k * D;
        ull* dst = sp + k * PSTRIDE;
        float b = 0.f;
        for (int j = 0; j <= i; ++j) {
            float lo, hi;
            up2(dst[tidx(i, j)], lo, hi);
            b = fmaf(lo, mu[j], b);
        }
        float nb = -b;
        dst[TRI + i] = pk2(nb, nb);
    }
    __syncthreads();

    // ---- Stage B: main loop (fully unrolled over k, logits deferred) --------
    const float4* __restrict__ X4 = reinterpret_cast<const float4*>(X);
    const int n0 = chunk * (N_POINTS / CHUNKS) + tid;   // chunk of 512 points

    // 4 points as 2 pairs: (n0, n0+128), (n0+256, n0+384)
    ull xp[NPAIR][D];
    #pragma unroll
    for (int pr = 0; pr < NPAIR; ++pr) {
        const int na = n0 + (2 * pr) * THREADS;
        const int nb = na + THREADS;
        float4 a0 = X4[2 * na], a1 = X4[2 * na + 1];
        float4 b0 = X4[2 * nb], b1 = X4[2 * nb + 1];
        xp[pr][0] = pk2(a0.x, b0.x); xp[pr][1] = pk2(a0.y, b0.y);
        xp[pr][2] = pk2(a0.z, b0.z); xp[pr][3] = pk2(a0.w, b0.w);
        xp[pr][4] = pk2(a1.x, b1.x); xp[pr][5] = pk2(a1.y, b1.y);
        xp[pr][6] = pk2(a1.z, b1.z); xp[pr][7] = pk2(a1.w, b1.w);
    }

    const ull NEG1 = pk2(-1.f, -1.f);
    ull lp[2 * K];   // packed logits, all components kept in registers

    #pragma unroll
    for (int k = 0; k < K; ++k) {
        const ull* __restrict__ w = sp + k * PSTRIDE;

        ull maha0 = 0ull, maha1 = 0ull;
        #pragma unroll
        for (int i = 0; i < D; ++i) {
            const ull nb = w[TRI + i];
            ull a0 = nb, a1 = nb;
            #pragma unroll
            for (int j = 0; j <= i; ++j) {
                const ull wv = w[tidx(i, j)];
                a0 = fma2(wv, xp[0][j], a0);
                a1 = fma2(wv, xp[1][j], a1);
            }
            maha0 = fma2(a0, a0, maha0);
            maha1 = fma2(a1, a1, maha1);
        }
        const ull c2p = w[TRI + D];
        lp[2 * k]     = fma2(maha0, NEG1, c2p);   // c2 - maha (exact)
        lp[2 * k + 1] = fma2(maha1, NEG1, c2p);
    }

    // one-shot logsumexp epilogue per point (tree max, independent ex2s)
    float acc = 0.f;
    #pragma unroll
    for (int pr = 0; pr < NPAIR; ++pr) {
        float la[K], lb[K];
        #pragma unroll
        for (int k = 0; k < K; ++k) up2(lp[2 * k + pr], la[k], lb[k]);

        float ma01 = fmaxf(la[0], la[1]), ma23 = fmaxf(la[2], la[3]);
        float ma45 = fmaxf(la[4], la[5]), ma67 = fmaxf(la[6], la[7]);
        float mxa = fmaxf(fmaxf(ma01, ma23), fmaxf(ma45, ma67));
        float sa = ((ex2a(la[0] - mxa) + ex2a(la[1] - mxa)) +
                    (ex2a(la[2] - mxa) + ex2a(la[3] - mxa))) +
                   ((ex2a(la[4] - mxa) + ex2a(la[5] - mxa)) +
                    (ex2a(la[6] - mxa) + ex2a(la[7] - mxa)));

        float mb01 = fmaxf(lb[0], lb[1]), mb23 = fmaxf(lb[2], lb[3]);
        float mb45 = fmaxf(lb[4], lb[5]), mb67 = fmaxf(lb[6], lb[7]);
        float mxb = fmaxf(fmaxf(mb01, mb23), fmaxf(mb45, mb67));
        float sb = ((ex2a(lb[0] - mxb) + ex2a(lb[1] - mxb)) +
                    (ex2a(lb[2] - mxb) + ex2a(lb[3] - mxb))) +
                   ((ex2a(lb[4] - mxb) + ex2a(lb[5] - mxb)) +
                    (ex2a(lb[6] - mxb) + ex2a(lb[7] - mxb)));

        acc += (mxa + lg2a(sa)) + (mxb + lg2a(sb));
    }
    acc *= 0.6931471805599453f;  // back to natural log

    // ---- Stage C: reduce + finalize -----------------------------------------
    red[tid] = acc;
    __syncthreads();
    #pragma unroll
    for (int s = THREADS / 2; s > 0; s >>= 1) {
        if (tid < s) {
            red[tid] += red[tid + s];
            redp[tid] += redp[tid + s];
        }
        __syncthreads();
    }

    if (tid == 0) {
        g_partial[m * CHUNKS + chunk] = red[0];
        __threadfence();
        const int old = atomicAdd(&g_count[m], 1);
        if (old == CHUNKS - 1) {
            __threadfence();
            double s = 0.0;
            #pragma unroll
            for (int c = 0; c < CHUNKS; ++c)
                s += (double)__ldcg(&g_partial[m * CHUNKS + c]);
            out[m] = (float)(-s + 0.005 * (double)redp[0]);  // 0.5*LAMBDA_PRIOR
            g_count[m] = 0;  // self-reset for next launch
        }
    }
}

extern "C" void kernel_launch(void* const* d_in, const int* in_sizes, int n_in,
                              void* d_out, int out_size) {
    const float* phi = (const float*)d_in[0];  // (32, 360)
    const float* X   = (const float*)d_in[1];  // (32768, 8)
    float* out = (float*)d_out;                // (32,)

    fused_kernel<<<M_MODELS * CHUNKS, THREADS>>>(phi, X, out);
}

// round 8
// speedup vs baseline: 1.3133x; 1.3133x over previous
#include <cuda_runtime.h>
#include <math_constants.h>

#define K 8
#define D 8
#define TRI 36
#define PHI_DIM 360         // K + K*D + K*TRI
#define M_MODELS 32
#define N_POINTS 32768
#define CHUNKS 32
#define THREADS 256
#define NPAIR 2             // 2 packed pairs = 4 points per thread
#define PSTRIDE 45          // per-(m,k): 36 Linv + 8 bias + 1 const (flat R4 layout)

typedef unsigned long long ull;

// Scratch (no allocations allowed)
__device__ float g_partial[M_MODELS * CHUNKS];
__device__ int   g_count[M_MODELS];          // zero-init; self-resetting

__host__ __device__ __forceinline__ constexpr int tidx(int i, int j) {
    return i * (i + 1) / 2 + j;
}

// ---- packed f32x2 helpers ---------------------------------------------------
__device__ __forceinline__ ull pk2(float lo, float hi) {
    ull r; asm("mov.b64 %0,{%1,%2};" : "=l"(r) : "f"(lo), "f"(hi)); return r;
}
__device__ __forceinline__ void up2(ull v, float& lo, float& hi) {
    asm("mov.b64 {%0,%1},%2;" : "=f"(lo), "=f"(hi) : "l"(v));
}
__device__ __forceinline__ ull fma2(ull a, ull b, ull c) {
    ull r; asm("fma.rn.f32x2 %0,%1,%2,%3;" : "=l"(r) : "l"(a), "l"(b), "l"(c)); return r;
}
__device__ __forceinline__ float ex2a(float x) {
    float r; asm("ex2.approx.ftz.f32 %0,%1;" : "=f"(r) : "f"(x)); return r;
}
__device__ __forceinline__ float lg2a(float x) {
    float r; asm("lg2.approx.ftz.f32 %0,%1;" : "=f"(r) : "f"(x)); return r;
}

// ---------------------------------------------------------------------------
// Single fused kernel. grid = 1024 blocks x 256 threads, 4 CTAs/SM (R4 config).
// Inner loop: 4 iterations x 2 components; merged pairwise logsumexp update.
// ---------------------------------------------------------------------------
__global__ void __launch_bounds__(THREADS, 4) fused_kernel(const float* __restrict__ phi,
                                                           const float* __restrict__ X,
                                                           float* __restrict__ out) {
    const int m = blockIdx.x >> 5;
    const int chunk = blockIdx.x & (CHUNKS - 1);
    const int tid = threadIdx.x;
    const float* pm = phi + m * PHI_DIM;

    __shared__ ull sp[K * PSTRIDE];
    __shared__ float red[THREADS];
    __shared__ float redp[THREADS];

    // ---- prior partial -------------------------------------------------------
    float pp = 0.f;
    #pragma unroll
    for (int i = tid; i < PHI_DIM; i += THREADS) {
        float v = pm[i];
        pp = fmaf(v, v, pp);
    }
    redp[tid] = pp;

    // ---- Stage A: build params in shared (threads 0-63, column-parallel) ----
    if (tid < 64) {
        const int k = tid >> 3;
        const int j = tid & 7;
        const float* Lk = pm + K + K * D + k * TRI;
        ull* dst = sp + k * PSTRIDE;
        const float SCALE = 0.8493218002880191f;  // sqrt(0.5*log2(e))

        float col[D];
        col[j] = __fdividef(1.f, Lk[tidx(j, j)]);
        for (int i = j + 1; i < D; ++i) {
            float acc = 0.f;
            for (int p = j; p < i; ++p)
                acc = fmaf(Lk[tidx(i, p)], col[p], acc);
            col[i] = -acc * __fdividef(1.f, Lk[tidx(i, i)]);
        }
        for (int i = j; i < D; ++i) {
            float v = col[i] * SCALE;
            dst[tidx(i, j)] = pk2(v, v);
        }

        if (j == 0) {
            float mx = -CUDART_INF_F;
            #pragma unroll
            for (int q = 0; q < K; ++q) mx = fmaxf(mx, pm[q]);
            float s = 0.f;
            #pragma unroll
            for (int q = 0; q < K; ++q) s += __expf(pm[q] - mx);
            const float log_pi = pm[k] - mx - __logf(s);

            float ld = 0.f;
            #pragma unroll
            for (int i = 0; i < D; ++i)
                ld += __logf(fmaxf(fabsf(Lk[tidx(i, i)]), 1e-8f));
            ld *= 2.f;

            const float c = log_pi - 0.5f * (D * 1.8378770664093453f + ld);
            const float c2 = c * 1.4426950408889634f;
            dst[TRI + D] = pk2(c2, c2);
        }
    }
    __syncthreads();

    // bias: nb_i = -sum_{j<=i} Linv_scaled[i][j] * mu[j]
    if (tid < 64) {
        const int k = tid >> 3;
        const int i = tid & 7;
        const float* mu = pm + K + k * D;
        ull* dst = sp + k * PSTRIDE;
        float b = 0.f;
        for (int j = 0; j <= i; ++j) {
            float lo, hi;
            up2(dst[tidx(i, j)], lo, hi);
            b = fmaf(lo, mu[j], b);
        }
        float nb = -b;
        dst[TRI + i] = pk2(nb, nb);
    }
    __syncthreads();

    // ---- Stage B: main loop --------------------------------------------------
    const float4* __restrict__ X4 = reinterpret_cast<const float4*>(X);
    const int n0 = chunk * (N_POINTS / CHUNKS) + tid;

    // 4 points as 2 pairs: (n0, n0+256), (n0+512, n0+768)
    ull xp[NPAIR][D];
    #pragma unroll
    for (int pr = 0; pr < NPAIR; ++pr) {
        const int na = n0 + (2 * pr) * THREADS;
        const int nb = na + THREADS;
        float4 a0 = X4[2 * na], a1 = X4[2 * na + 1];
        float4 b0 = X4[2 * nb], b1 = X4[2 * nb + 1];
        xp[pr][0] = pk2(a0.x, b0.x); xp[pr][1] = pk2(a0.y, b0.y);
        xp[pr][2] = pk2(a0.z, b0.z); xp[pr][3] = pk2(a0.w, b0.w);
        xp[pr][4] = pk2(a1.x, b1.x); xp[pr][5] = pk2(a1.y, b1.y);
        xp[pr][6] = pk2(a1.z, b1.z); xp[pr][7] = pk2(a1.w, b1.w);
    }

    float mx[2 * NPAIR], sm[2 * NPAIR];
    #pragma unroll
    for (int p = 0; p < 2 * NPAIR; ++p) { mx[p] = -CUDART_INF_F; sm[p] = 0.f; }

    const ull NEG1 = pk2(-1.f, -1.f);

    #pragma unroll 1
    for (int kk = 0; kk < K / 2; ++kk) {
        const ull* __restrict__ wA = sp + (2 * kk) * PSTRIDE;
        const ull* __restrict__ wB = sp + (2 * kk + 1) * PSTRIDE;

        // component A: both point-pairs
        ull mahaA0 = 0ull, mahaA1 = 0ull;
        #pragma unroll
        for (int i = 0; i < D; ++i) {
            const ull nb = wA[TRI + i];
            ull a0 = nb, a1 = nb;
            #pragma unroll
            for (int j = 0; j <= i; ++j) {
                const ull wv = wA[tidx(i, j)];
                a0 = fma2(wv, xp[0][j], a0);
                a1 = fma2(wv, xp[1][j], a1);
            }
            mahaA0 = fma2(a0, a0, mahaA0);
            mahaA1 = fma2(a1, a1, mahaA1);
        }
        // component B: both point-pairs
        ull mahaB0 = 0ull, mahaB1 = 0ull;
        #pragma unroll
        for (int i = 0; i < D; ++i) {
            const ull nb = wB[TRI + i];
            ull a0 = nb, a1 = nb;
            #pragma unroll
            for (int j = 0; j <= i; ++j) {
                const ull wv = wB[tidx(i, j)];
                a0 = fma2(wv, xp[0][j], a0);
                a1 = fma2(wv, xp[1][j], a1);
            }
            mahaB0 = fma2(a0, a0, mahaB0);
            mahaB1 = fma2(a1, a1, mahaB1);
        }

        // packed logits: l = c2 - maha
        const ull lA0 = fma2(mahaA0, NEG1, wA[TRI + D]);
        const ull lA1 = fma2(mahaA1, NEG1, wA[TRI + D]);
        const ull lB0 = fma2(mahaB0, NEG1, wB[TRI + D]);
        const ull lB1 = fma2(mahaB1, NEG1, wB[TRI + D]);

        float la[4], lb[4];
        up2(lA0, la[0], la[1]);
        up2(lA1, la[2], la[3]);
        up2(lB0, lb[0], lb[1]);
        up2(lB1, lb[2], lb[3]);

        // merged pairwise streaming update: one chain step per 2 components
        #pragma unroll
        for (int p = 0; p < 4; ++p) {
            const float lm = fmaxf(la[p], lb[p]);
            const float nm = fmaxf(mx[p], lm);
            sm[p] = fmaf(sm[p], ex2a(mx[p] - nm),
                         ex2a(la[p] - nm) + ex2a(lb[p] - nm));
            mx[p] = nm;
        }
    }

    float acc = 0.f;
    #pragma unroll
    for (int p = 0; p < 2 * NPAIR; ++p)
        acc += mx[p] + lg2a(sm[p]);
    acc *= 0.6931471805599453f;  // back to natural log

    // ---- Stage C: reduce + finalize -----------------------------------------
    red[tid] = acc;
    __syncthreads();
    #pragma unroll
    for (int s = THREADS / 2; s > 0; s >>= 1) {
        if (tid < s) {
            red[tid] += red[tid + s];
            redp[tid] += redp[tid + s];
        }
        __syncthreads();
    }

    if (tid == 0) {
        g_partial[m * CHUNKS + chunk] = red[0];
        __threadfence();
        const int old = atomicAdd(&g_count[m], 1);
        if (old == CHUNKS - 1) {
            __threadfence();
            double s = 0.0;
            #pragma unroll
            for (int c = 0; c < CHUNKS; ++c)
                s += (double)__ldcg(&g_partial[m * CHUNKS + c]);
            out[m] = (float)(-s + 0.005 * (double)redp[0]);  // 0.5*LAMBDA_PRIOR
            g_count[m] = 0;  // self-reset for next launch
        }
    }
}

extern "C" void kernel_launch(void* const* d_in, const int* in_sizes, int n_in,
                              void* d_out, int out_size) {
    const float* phi = (const float*)d_in[0];  // (32, 360)
    const float* X   = (const float*)d_in[1];  // (32768, 8)
    float* out = (float*)d_out;                // (32,)

    fused_kernel<<<M_MODELS * CHUNKS, THREADS>>>(phi, X, out);
}